// round 3
// baseline (speedup 1.0000x reference)
#include <cuda_runtime.h>
#include <stdint.h>

// ---------------------------------------------------------------------------
// OneHopGCNNormNodeLabelAggregator
//   deg[i]   = 1 + #{e : row[e]==i}
//   dis[i]   = rsqrt(deg[i])
//   out[c,:] = dis[c]^2 * x[c,:] + sum_{e: col[e]==c} dis[row[e]]*dis[c]*x[row[e],:]
// x [100000,64] f32, edge_index [2,1600000] (int32 OR int64 — detected at
// runtime), out [100000,64] f32.
//
// CSR-by-destination build, then warp-per-node gather aggregation.
// No floating-point atomics anywhere.
// ---------------------------------------------------------------------------

#define MAX_NODES 131072
#define MAX_EDGES 1700000
#define FEAT 64
#define FEAT2 32   // 64 floats = 32 float2 per row

__device__ int   g_is64;                // 1 if edge_index is int64, 0 if int32
__device__ int   g_deg[MAX_NODES];      // degree over rows (incl. self loop)
__device__ int   g_cnt[MAX_NODES];      // in-degree per col (excl. self loop)
__device__ int   g_off[MAX_NODES + 1];  // exclusive scan of g_cnt
__device__ int   g_cur[MAX_NODES];      // scatter cursors
__device__ float g_dis[MAX_NODES];      // rsqrt(deg)
__device__ int   g_src[MAX_EDGES];      // CSR: source node per incoming edge

// Read element e of the row (part==0) or col (part==1) array, either dtype.
__device__ __forceinline__ int load_idx(const void* ei, int part, int e,
                                        int n_edges, int is64) {
    if (is64) {
        return (int)((const long long*)ei)[(long long)part * n_edges + e];
    } else {
        return ((const int*)ei)[(long long)part * n_edges + e];
    }
}

// --- pass 0: detect index dtype ----------------------------------------------
__global__ void k_detect(const void* ei, int n) {
    const long long* p = (const long long*)ei;
    int ok = 1;
#pragma unroll
    for (int i = 0; i < 16; i++) {
        long long v = p[i];
        if (v < 0 || v >= (long long)n) ok = 0;
    }
    g_is64 = ok;
}

// --- pass 1: reset counters (graph replays must be idempotent) ----------------
__global__ void k_init(int n) {
    int i = blockIdx.x * blockDim.x + threadIdx.x;
    if (i < n) {
        g_deg[i] = 1;   // self loop
        g_cnt[i] = 0;
        g_cur[i] = 0;
    }
}

// --- pass 2: degree over rows + in-count over cols -----------------------------
__global__ void k_count(const void* __restrict__ ei, int n_edges) {
    int e = blockIdx.x * blockDim.x + threadIdx.x;
    if (e < n_edges) {
        int is64 = g_is64;
        int r = load_idx(ei, 0, e, n_edges, is64);
        int c = load_idx(ei, 1, e, n_edges, is64);
        atomicAdd(&g_deg[r], 1);
        atomicAdd(&g_cnt[c], 1);
    }
}

__global__ void k_dis(int n) {
    int i = blockIdx.x * blockDim.x + threadIdx.x;
    if (i < n) g_dis[i] = rsqrtf((float)g_deg[i]);
}

// --- pass 3: single-block exclusive scan of g_cnt -> g_off ---------------------
__global__ void k_scan(int n) {
    __shared__ int warp_sums[32];
    __shared__ int carry_s;
    const int T = 1024;
    int tid = threadIdx.x;
    int lane = tid & 31, wid = tid >> 5;
    if (tid == 0) carry_s = 0;
    __syncthreads();
    for (int base = 0; base < n; base += T * 4) {
        int v[4];
        int idx = base + tid * 4;
        int s = 0;
#pragma unroll
        for (int k = 0; k < 4; k++) {
            v[k] = (idx + k < n) ? g_cnt[idx + k] : 0;
            s += v[k];
        }
        int xs = s;  // inclusive warp scan of per-thread sums
#pragma unroll
        for (int d = 1; d < 32; d <<= 1) {
            int y = __shfl_up_sync(0xFFFFFFFFu, xs, d);
            if (lane >= d) xs += y;
        }
        if (lane == 31) warp_sums[wid] = xs;
        __syncthreads();
        if (wid == 0) {
            int w = warp_sums[lane];
#pragma unroll
            for (int d = 1; d < 32; d <<= 1) {
                int y = __shfl_up_sync(0xFFFFFFFFu, w, d);
                if (lane >= d) w += y;
            }
            warp_sums[lane] = w;
        }
        __syncthreads();
        int warp_excl = (wid == 0) ? 0 : warp_sums[wid - 1];
        int te = carry_s + warp_excl + (xs - s);   // exclusive prefix
#pragma unroll
        for (int k = 0; k < 4; k++) {
            if (idx + k < n) g_off[idx + k] = te;
            te += v[k];
        }
        __syncthreads();
        if (tid == 0) carry_s += warp_sums[31];
        __syncthreads();
    }
    if (tid == 0) g_off[n] = carry_s;
}

// --- pass 4: bucket-scatter source ids by destination ---------------------------
__global__ void k_scatter(const void* __restrict__ ei, int n_edges) {
    int e = blockIdx.x * blockDim.x + threadIdx.x;
    if (e < n_edges) {
        int is64 = g_is64;
        int r = load_idx(ei, 0, e, n_edges, is64);
        int c = load_idx(ei, 1, e, n_edges, is64);
        int pos = atomicAdd(&g_cur[c], 1);
        g_src[g_off[c] + pos] = r;
    }
}

// --- pass 5: warp-per-node aggregation (no FP atomics) ---------------------------
__global__ void k_agg(const float2* __restrict__ x, float2* __restrict__ out, int n) {
    int warp = (blockIdx.x * blockDim.x + threadIdx.x) >> 5;
    int lane = threadIdx.x & 31;
    if (warp >= n) return;
    float dc = g_dis[warp];
    float2 xv = x[warp * FEAT2 + lane];
    float w0 = dc * dc;                 // self-loop weight
    float accx = w0 * xv.x, accy = w0 * xv.y;
    int beg = g_off[warp], end = g_off[warp + 1];
    for (int j = beg; j < end; j++) {
        int r = g_src[j];               // uniform across the warp -> broadcast
        float w = dc * g_dis[r];
        float2 v = x[r * FEAT2 + lane]; // coalesced 256B gather
        accx += w * v.x;
        accy += w * v.y;
    }
    out[warp * FEAT2 + lane] = make_float2(accx, accy);
}

extern "C" void kernel_launch(void* const* d_in, const int* in_sizes, int n_in,
                              void* d_out, int out_size) {
    const float* x  = (const float*)d_in[0];   // [n, 64]
    const void*  ei = d_in[1];                 // [2, E] int32 or int64
    float* out = (float*)d_out;

    const int n       = in_sizes[0] / FEAT;   // 100000
    const int n_edges = in_sizes[1] / 2;      // 1600000

    const int TPB = 256;

    k_detect<<<1, 1>>>(ei, n);
    k_init<<<(n + TPB - 1) / TPB, TPB>>>(n);
    k_count<<<(n_edges + TPB - 1) / TPB, TPB>>>(ei, n_edges);
    k_dis<<<(n + TPB - 1) / TPB, TPB>>>(n);
    k_scan<<<1, 1024>>>(n);
    k_scatter<<<(n_edges + TPB - 1) / TPB, TPB>>>(ei, n_edges);

    long long agg_threads = (long long)n * 32;
    k_agg<<<(int)((agg_threads + TPB - 1) / TPB), TPB>>>(
        (const float2*)x, (float2*)out, n);
}

// round 4
// speedup vs baseline: 1.4162x; 1.4162x over previous
#include <cuda_runtime.h>
#include <stdint.h>

// ---------------------------------------------------------------------------
// OneHopGCNNormNodeLabelAggregator — CSR-by-destination + warp-per-node gather.
//   deg[i]   = 1 + #{e : row[e]==i}
//   dis[i]   = rsqrt(deg[i])
//   out[c,:] = dis[c]^2 * x[c,:] + sum_{e: col[e]==c} dis[row[e]]*dis[c]*x[row[e],:]
// x [100000,64] f32, edge_index [2,1600000] int32-or-int64 (runtime detect),
// out [100000,64] f32. No floating-point atomics anywhere.
// ---------------------------------------------------------------------------

#define MAX_NODES 131072
#define MAX_EDGES 1700000
#define FEAT 64
#define FEAT2 32
#define SCAN_TPB 512
#define SCAN_PER_BLOCK (SCAN_TPB * 4)   // 2048 elements per scan block
#define MAX_SCAN_BLOCKS 128

__device__ int   g_is64;
__device__ int   g_deg[MAX_NODES];       // row-degree incl. self loop
__device__ int   g_cnt[MAX_NODES];       // in-count per col (excl. self loop)
__device__ int   g_off[MAX_NODES + 1];   // exclusive scan of g_cnt
__device__ int   g_cur[MAX_NODES];       // scatter cursors (init = g_off)
__device__ float g_dis[MAX_NODES];       // rsqrt(deg)
__device__ int   g_bsum[MAX_SCAN_BLOCKS + 1];
__device__ int   g_src[MAX_EDGES];       // CSR payload: source per incoming edge

__device__ __forceinline__ int load_idx(const void* ei, int part, int e,
                                        int n_edges, int is64) {
    if (is64) return (int)((const long long*)ei)[(long long)part * n_edges + e];
    return ((const int*)ei)[(long long)part * n_edges + e];
}

// --- init counters + dtype detection -----------------------------------------
__global__ void k_init(const void* ei, int n) {
    int i = blockIdx.x * blockDim.x + threadIdx.x;
    if (i < n) {
        g_deg[i] = 1;   // self loop
        g_cnt[i] = 0;
    }
    if (i == 0) {
        const long long* p = (const long long*)ei;
        int ok = 1;
#pragma unroll
        for (int k = 0; k < 16; k++) {
            long long v = p[k];
            if (v < 0 || v >= (long long)n) ok = 0;
        }
        g_is64 = ok;
    }
}

// --- per-edge counting --------------------------------------------------------
__global__ void k_count(const void* __restrict__ ei, int n_edges) {
    int e = blockIdx.x * blockDim.x + threadIdx.x;
    if (e < n_edges) {
        int is64 = g_is64;
        atomicAdd(&g_deg[load_idx(ei, 0, e, n_edges, is64)], 1);
        atomicAdd(&g_cnt[load_idx(ei, 1, e, n_edges, is64)], 1);
    }
}

// --- scan phase A: per-block sums of g_cnt; fused g_dis computation ------------
__global__ void k_scanA(int n) {
    __shared__ int warp_sums[SCAN_TPB / 32];
    int tid = threadIdx.x, lane = tid & 31, wid = tid >> 5;
    int base = blockIdx.x * SCAN_PER_BLOCK;
    int s = 0;
#pragma unroll
    for (int k = 0; k < 4; k++) {
        int idx = base + tid + k * SCAN_TPB;
        if (idx < n) {
            s += g_cnt[idx];
            g_dis[idx] = rsqrtf((float)g_deg[idx]);   // fused elementwise pass
        }
    }
#pragma unroll
    for (int d = 16; d > 0; d >>= 1) s += __shfl_down_sync(0xFFFFFFFFu, s, d);
    if (lane == 0) warp_sums[wid] = s;
    __syncthreads();
    if (wid == 0) {
        int v = (lane < SCAN_TPB / 32) ? warp_sums[lane] : 0;
#pragma unroll
        for (int d = 16; d > 0; d >>= 1) v += __shfl_down_sync(0xFFFFFFFFu, v, d);
        if (lane == 0) g_bsum[blockIdx.x] = v;
    }
}

// --- scan phase B: exclusive scan of block sums (one small block) ---------------
__global__ void k_scanB(int nblocks, int n) {
    int tid = threadIdx.x, lane = tid & 31, wid = tid >> 5;
    __shared__ int ws[4];
    int v = (tid < nblocks) ? g_bsum[tid] : 0;
    int xs = v;
#pragma unroll
    for (int d = 1; d < 32; d <<= 1) {
        int y = __shfl_up_sync(0xFFFFFFFFu, xs, d);
        if (lane >= d) xs += y;
    }
    if (lane == 31) ws[wid] = xs;
    __syncthreads();
    int carry = 0;
#pragma unroll
    for (int w = 0; w < 4; w++) {
        if (w < wid) carry += ws[w];
    }
    int excl = carry + xs - v;
    if (tid < nblocks) g_bsum[tid] = excl;
    if (tid == nblocks - 1) {
        g_bsum[nblocks] = excl + v;
        g_off[n] = excl + v;   // total edge count
    }
}

// --- scan phase C: block-local exclusive scan + offset; init cursors ------------
__global__ void k_scanC(int n) {
    __shared__ int warp_sums[SCAN_TPB / 32];
    int tid = threadIdx.x, lane = tid & 31, wid = tid >> 5;
    int base = blockIdx.x * SCAN_PER_BLOCK;
    int idx = base + tid * 4;                  // contiguous 4 per thread
    int v[4];
    int s = 0;
#pragma unroll
    for (int k = 0; k < 4; k++) {
        v[k] = (idx + k < n) ? g_cnt[idx + k] : 0;
        s += v[k];
    }
    int xs = s;
#pragma unroll
    for (int d = 1; d < 32; d <<= 1) {
        int y = __shfl_up_sync(0xFFFFFFFFu, xs, d);
        if (lane >= d) xs += y;
    }
    if (lane == 31) warp_sums[wid] = xs;
    __syncthreads();
    if (wid == 0) {
        int w = (lane < SCAN_TPB / 32) ? warp_sums[lane] : 0;
#pragma unroll
        for (int d = 1; d < 32; d <<= 1) {
            int y = __shfl_up_sync(0xFFFFFFFFu, w, d);
            if (lane >= d) w += y;
        }
        if (lane < SCAN_TPB / 32) warp_sums[lane] = w;
    }
    __syncthreads();
    int warp_excl = (wid == 0) ? 0 : warp_sums[wid - 1];
    int te = g_bsum[blockIdx.x] + warp_excl + (xs - s);
#pragma unroll
    for (int k = 0; k < 4; k++) {
        if (idx + k < n) {
            g_off[idx + k] = te;
            g_cur[idx + k] = te;   // cursor starts at segment base
        }
        te += v[k];
    }
}

// --- bucket-scatter source ids by destination -----------------------------------
__global__ void k_scatter(const void* __restrict__ ei, int n_edges) {
    int e = blockIdx.x * blockDim.x + threadIdx.x;
    if (e < n_edges) {
        int is64 = g_is64;
        int r = load_idx(ei, 0, e, n_edges, is64);
        int c = load_idx(ei, 1, e, n_edges, is64);
        int pos = atomicAdd(&g_cur[c], 1);
        g_src[pos] = r;
    }
}

// --- warp-per-node aggregation (no FP atomics), 2x unrolled ----------------------
__global__ void k_agg(const float2* __restrict__ x, float2* __restrict__ out, int n) {
    int warp = (blockIdx.x * blockDim.x + threadIdx.x) >> 5;
    int lane = threadIdx.x & 31;
    if (warp >= n) return;
    float dc = g_dis[warp];
    float2 xv = x[warp * FEAT2 + lane];
    float w0 = dc * dc;
    float ax = w0 * xv.x, ay = w0 * xv.y;
    float bx = 0.f, by = 0.f;
    int beg = g_off[warp], end = g_off[warp + 1];
    int j = beg;
    for (; j + 2 <= end; j += 2) {
        int r0 = g_src[j];
        int r1 = g_src[j + 1];
        float wA = dc * g_dis[r0];
        float wB = dc * g_dis[r1];
        float2 v0 = x[r0 * FEAT2 + lane];
        float2 v1 = x[r1 * FEAT2 + lane];
        ax += wA * v0.x;  ay += wA * v0.y;
        bx += wB * v1.x;  by += wB * v1.y;
    }
    if (j < end) {
        int r0 = g_src[j];
        float wA = dc * g_dis[r0];
        float2 v0 = x[r0 * FEAT2 + lane];
        ax += wA * v0.x;  ay += wA * v0.y;
    }
    out[warp * FEAT2 + lane] = make_float2(ax + bx, ay + by);
}

extern "C" void kernel_launch(void* const* d_in, const int* in_sizes, int n_in,
                              void* d_out, int out_size) {
    const float* x  = (const float*)d_in[0];
    const void*  ei = d_in[1];
    float* out = (float*)d_out;

    const int n       = in_sizes[0] / FEAT;   // 100000
    const int n_edges = in_sizes[1] / 2;      // 1600000
    const int TPB = 256;
    const int nscan = (n + SCAN_PER_BLOCK - 1) / SCAN_PER_BLOCK;   // 49

    k_init<<<(n + TPB - 1) / TPB, TPB>>>(ei, n);
    k_count<<<(n_edges + TPB - 1) / TPB, TPB>>>(ei, n_edges);
    k_scanA<<<nscan, SCAN_TPB>>>(n);
    k_scanB<<<1, 128>>>(nscan, n);
    k_scanC<<<nscan, SCAN_TPB>>>(n);
    k_scatter<<<(n_edges + TPB - 1) / TPB, TPB>>>(ei, n_edges);

    long long agg_threads = (long long)n * 32;
    k_agg<<<(int)((agg_threads + TPB - 1) / TPB), TPB>>>(
        (const float2*)x, (float2*)out, n);
}